// round 15
// baseline (speedup 1.0000x reference)
#include <cuda_runtime.h>
#include <math.h>

#define BATCH 32
#define SEQ 4096
#define HIDDEN 2048
#define ROUTE_H 256
#define NUM_EXPERTS 64
#define TOP_K 8
#define LN_EPS 1e-5f

#define NTHR 512
#define NBLK 512                     // one co-resident wave (148 SMs x 4 max)
#define NSTEP 4                      // pool items per block
#define ITEMS (NBLK * NSTEP)         // 2048 items
#define IPB (ITEMS / BATCH)          // 64 items per batch
#define PROWS (SEQ / IPB)            // 64 seq rows per item
#define H4 (HIDDEN / 4)              // 512 float4 columns

#define GSPLIT 16                    // GEMV1 K-slices per batch
#define KCHUNK (HIDDEN / GSPLIT)     // 128 hidden rows per slice

// Scratch (no cudaMalloc allowed). Zero-init at load; counters reset by each
// batch's finale after all uses -> graph-replay safe.
__device__ float g_partial[ITEMS * HIDDEN];            // [item][h] = 16 MB
__device__ float g_hpart[GSPLIT * BATCH * ROUTE_H];    // [gs][b][j] = 512 KB
__device__ unsigned int g_done[BATCH];                 // pooled items per batch
__device__ unsigned int g_cnt2[BATCH];                 // gemv slices per batch

// ---------------------------------------------------------------------------
// ONE fused kernel, 512 blocks x 512 threads, forced 4 blocks/SM (32 regs) so
// the whole grid is co-resident and the final spin-wait cannot deadlock.
// Static staggered schedule: step q pools item q*512+blk (batch-major), so
// batches [8q, 8q+8) finish pooling at ~(q+1)/4 of the stream. After each
// item a block checks (no spin) whether its GEMV batch is ready and, if so,
// runs its fold + GEMV1 slice (+ election + finale) mid-stream, hidden under
// other blocks' streaming; then it resumes pooling. Only the last 8 batches'
// router work is exposed after the stream. Every block does exactly one GEMV
// -> balanced. All reduction orders fixed -> deterministic.
// ---------------------------------------------------------------------------
__global__ void __launch_bounds__(NTHR, 4) fused_router(
    const float* __restrict__ x,
    const float* __restrict__ W1, const float* __restrict__ b1,
    const float* __restrict__ ln_g, const float* __restrict__ ln_b,
    const float* __restrict__ W2, const float* __restrict__ b2,
    float* __restrict__ out)
{
    __shared__ float sh_fold[4][KCHUNK];
    __shared__ float sh_pool[KCHUNK];
    __shared__ float sh_gacc[2][ROUTE_H];
    __shared__ float sh_h[ROUTE_H];
    __shared__ float sh_w1r[8], sh_w2r[8];
    __shared__ float sh_part[ROUTE_H];
    __shared__ float sh_logits[NUM_EXPERTS];
    __shared__ unsigned int s_go, s_flag;

    int blk = blockIdx.x;
    int t   = threadIdx.x;           // 0..511
    int gb  = blk >> 4;              // this block's GEMV batch 0..31
    int gs  = blk & (GSPLIT - 1);    // this block's GEMV K-slice 0..15

    bool gemv_done = false;

#pragma unroll 1
    for (int q = 0; q <= NSTEP; q++) {
        // ---------------- pool one 64-row item (steps 0..3) ----------------
        if (q < NSTEP) {
            int item = q * NBLK + blk;
            int pb   = item / IPB;               // batch (batch-major)
            int ps   = item % IPB;

            const float4* base = (const float4*)(x) +
                ((size_t)pb * SEQ + (size_t)ps * PROWS) * (size_t)H4 + t;
            float4 acc = make_float4(0.f, 0.f, 0.f, 0.f);
#pragma unroll 8
            for (int s = 0; s < PROWS; s++) {
                float4 v = __ldcs(&base[(size_t)s * H4]);
                acc.x += v.x; acc.y += v.y; acc.z += v.z; acc.w += v.w;
            }
            ((float4*)(g_partial + (size_t)item * HIDDEN))[t] = acc;

            __threadfence();                     // publish this item
            __syncthreads();
            if (t == 0) atomicAdd(&g_done[pb], 1u);
        }

        // ---------------- is my GEMV batch fully pooled? -------------------
        if (!gemv_done) {
            if (t == 0) {
                if (q == NSTEP) {
                    // all items issued; wait for stragglers (co-resident grid)
                    while (((volatile unsigned int*)g_done)[gb] < IPB) { }
                    s_go = 1u;
                } else {
                    s_go = (((volatile unsigned int*)g_done)[gb] >= IPB) ? 1u : 0u;
                }
            }
            __syncthreads();
            if (!s_go) continue;
            gemv_done = true;
            __threadfence();                     // acquire all 64 item slices

            // ---- fold 64 partials for cols [gs*128, +128) ----
            int i0 = gs * KCHUNK;
            {
                int col  = t & (KCHUNK - 1);
                int part = t >> 7;               // 0..3
                const float* p = g_partial +
                    ((size_t)gb * IPB + part * 16) * HIDDEN + i0 + col;
                float sA = 0.f, sB = 0.f;
#pragma unroll
                for (int u = 0; u < 8; u++) {
                    sA += p[(size_t)(2 * u)     * HIDDEN];
                    sB += p[(size_t)(2 * u + 1) * HIDDEN];
                }
                sh_fold[part][col] = sA + sB;
            }
            __syncthreads();
            if (t < KCHUNK) {
                sh_pool[t] = ((sh_fold[0][t] + sh_fold[1][t]) +
                              (sh_fold[2][t] + sh_fold[3][t])) * (1.0f / SEQ);
            }
            __syncthreads();

            // ---- GEMV1 slice: 256 outputs x 2 row-halves of 64 rows ----
            {
                int j    = t & (ROUTE_H - 1);
                int half = t >> 8;               // 0 or 1
                int r0   = i0 + half * 64;
                float a0 = 0.f, a1 = 0.f, a2 = 0.f, a3 = 0.f;
                float a4 = 0.f, a5 = 0.f, a6 = 0.f, a7 = 0.f;
#pragma unroll
                for (int r = 0; r < 64; r += 8) {
                    const float* w = W1 + (size_t)(r0 + r) * ROUTE_H + j;
                    int p = half * 64 + r;
                    a0 += sh_pool[p + 0] * w[0 * ROUTE_H];
                    a1 += sh_pool[p + 1] * w[1 * ROUTE_H];
                    a2 += sh_pool[p + 2] * w[2 * ROUTE_H];
                    a3 += sh_pool[p + 3] * w[3 * ROUTE_H];
                    a4 += sh_pool[p + 4] * w[4 * ROUTE_H];
                    a5 += sh_pool[p + 5] * w[5 * ROUTE_H];
                    a6 += sh_pool[p + 6] * w[6 * ROUTE_H];
                    a7 += sh_pool[p + 7] * w[7 * ROUTE_H];
                }
                sh_gacc[half][j] =
                    ((a0 + a1) + (a2 + a3)) + ((a4 + a5) + (a6 + a7));
            }
            __syncthreads();
            if (t < ROUTE_H)
                g_hpart[((size_t)gs * BATCH + gb) * ROUTE_H + t] =
                    sh_gacc[0][t] + sh_gacc[1][t];

            // ---- election: last slice of batch gb runs the finale ----
            __threadfence();                     // publish h-slice
            __syncthreads();
            if (t == 0) {
                unsigned int old = atomicAdd(&g_cnt2[gb], 1u);
                s_flag = (old == GSPLIT - 1) ? 1u : 0u;
            }
            __syncthreads();
            if (!s_flag) continue;
            __threadfence();                     // acquire all 16 h-slices

            // ---------------- finale (first 256 threads) ----------------
            if (t < ROUTE_H) {
                int j    = t;
                int lane = t & 31;
                int warp = t >> 5;

                float h = 0.f;
#pragma unroll
                for (int k = 0; k < GSPLIT; k++)
                    h += g_hpart[((size_t)k * BATCH + gb) * ROUTE_H + j];
                h += b1[j];

                float s1 = h, s2 = h * h;
#pragma unroll
                for (int o = 16; o > 0; o >>= 1) {
                    s1 += __shfl_xor_sync(0xffffffffu, s1, o);
                    s2 += __shfl_xor_sync(0xffffffffu, s2, o);
                }
                if (lane == 0) { sh_w1r[warp] = s1; sh_w2r[warp] = s2; }
                __syncwarp();
                asm volatile("bar.sync 1, 256;" ::: "memory");
                float t1 = sh_w1r[lane & 7], t2 = sh_w2r[lane & 7];
#pragma unroll
                for (int o = 4; o > 0; o >>= 1) {
                    t1 += __shfl_xor_sync(0xffffffffu, t1, o);
                    t2 += __shfl_xor_sync(0xffffffffu, t2, o);
                }
                t1 = __shfl_sync(0xffffffffu, t1, 0);
                t2 = __shfl_sync(0xffffffffu, t2, 0);

                float mu  = t1 * (1.0f / ROUTE_H);
                float ms  = t2 * (1.0f / ROUTE_H);
                float inv = rsqrtf(ms - mu * mu + LN_EPS);
                h = (h - mu) * inv * ln_g[j] + ln_b[j];
                h = 0.5f * h * (1.0f + erff(h * 0.70710678118654752f));
                sh_h[j] = h;
                asm volatile("bar.sync 1, 256;" ::: "memory");

                {   // GEMV2, K-split 4: 256 threads = 64 experts x 4 slices
                    int e   = j & (NUM_EXPERTS - 1);
                    int ks2 = j >> 6;
                    int r0  = ks2 * (ROUTE_H / 4);
                    float a = 0.f;
#pragma unroll 8
                    for (int i = 0; i < ROUTE_H / 4; i++)
                        a += sh_h[r0 + i] * W2[(size_t)(r0 + i) * NUM_EXPERTS + e];
                    sh_part[j] = a;
                }
                asm volatile("bar.sync 1, 256;" ::: "memory");
                if (j < NUM_EXPERTS) {
                    sh_logits[j] = ((sh_part[j] + sh_part[j + 64]) +
                                    (sh_part[j + 128] + sh_part[j + 192]))
                                   + b2[j];
                    out[(size_t)gb * NUM_EXPERTS + j] = 0.0f;  // d_out poisoned
                }
                asm volatile("bar.sync 1, 256;" ::: "memory");

                // top-8 + softmax + scatter (strict '>' = first-index
                // tie-break, matching jax.lax.top_k), then counter resets.
                if (j == 0) {
                    int   idx[TOP_K];
                    float val[TOP_K];
                    unsigned long long used = 0ull;
                    for (int k = 0; k < TOP_K; k++) {
                        float best = -INFINITY;
                        int bi = 0;
                        for (int e = 0; e < NUM_EXPERTS; e++) {
                            if (!((used >> e) & 1ull) && sh_logits[e] > best) {
                                best = sh_logits[e]; bi = e;
                            }
                        }
                        used |= (1ull << bi);
                        idx[k] = bi;
                        val[k] = best;
                    }
                    float mx = val[0];
                    float denom = 0.f;
                    float ex[TOP_K];
                    for (int k = 0; k < TOP_K; k++) {
                        ex[k] = expf(val[k] - mx); denom += ex[k];
                    }
                    float rden = 1.0f / denom;
                    for (int k = 0; k < TOP_K; k++)
                        out[(size_t)gb * NUM_EXPERTS + idx[k]] = ex[k] * rden;

                    // Safe: g_cnt2[gb]==16 means every slice block already
                    // observed g_done[gb]>=IPB; no future increments of
                    // g_done[gb] exist (its 64 items are all pooled).
                    g_done[gb] = 0u;
                    g_cnt2[gb] = 0u;
                }
            }
            __syncthreads();
        }
    }
}

// ---------------------------------------------------------------------------
extern "C" void kernel_launch(void* const* d_in, const int* in_sizes, int n_in,
                              void* d_out, int out_size) {
    const float* hs   = (const float*)d_in[0];
    const float* W1   = (const float*)d_in[1];
    const float* b1   = (const float*)d_in[2];
    const float* ln_g = (const float*)d_in[3];
    const float* ln_b = (const float*)d_in[4];
    const float* W2   = (const float*)d_in[5];
    const float* b2   = (const float*)d_in[6];
    // d_in[7] = top_k (hardcoded 8)

    float* out = (float*)d_out;

    fused_router<<<NBLK, NTHR>>>(hs, W1, b1, ln_g, ln_b, W2, b2, out);
}

// round 16
// speedup vs baseline: 1.0274x; 1.0274x over previous
#include <cuda_runtime.h>
#include <math.h>

#define BATCH 32
#define SEQ 4096
#define HIDDEN 2048
#define ROUTE_H 256
#define NUM_EXPERTS 64
#define TOP_K 8
#define LN_EPS 1e-5f

#define GSPLIT 16                    // blocks per batch = hidden-column slices
#define KCHUNK (HIDDEN / GSPLIT)     // 128 hidden cols per block
#define K4 (KCHUNK / 4)              // 32 float4 per row-slice
#define H4 (HIDDEN / 4)              // 512 float4 per full row
#define NTHR 512
#define NBLK (BATCH * GSPLIT)        // 512 blocks
#define RGROUPS 16                   // row groups per block (t>>5)
#define RPT (SEQ / RGROUPS)          // 256 rows per thread

// Scratch (no cudaMalloc). Zero-init at load; counter reset by each batch's
// finale after all uses complete -> graph-replay safe.
__device__ float g_hpart[GSPLIT * BATCH * ROUTE_H];    // [gs][b][j] = 512 KB
__device__ unsigned int g_cnt[BATCH];                  // gemv slices done

// ---------------------------------------------------------------------------
// ONE fused kernel, 512 blocks x 512 threads. Block (b, sp) owns hidden
// columns [sp*128, sp*128+128) of batch b:
//  Phase 1: stream ALL 4096 seq rows of its column slice (float4, __ldcs,
//    every 128B line touched exactly once chip-wide) and reduce directly to
//    pooled[slice] in shared. No cross-block dependency, no scratch partials,
//    NO SPIN-WAITS anywhere -> no co-residency requirement.
//  Phase 2: GEMV1 on its own slice immediately (blocks finish streaming at
//    staggered times, so W1 fetches overlap other blocks' tails).
//  Phase 3: atomic election; the 16th finisher of batch b runs
//    fold(16 h-slices) + LN + GELU + GEMV2 + top-8.
// All reduction orders fixed -> deterministic output.
// ---------------------------------------------------------------------------
__global__ void __launch_bounds__(NTHR) fused_router(
    const float* __restrict__ x,
    const float* __restrict__ W1, const float* __restrict__ b1,
    const float* __restrict__ ln_g, const float* __restrict__ ln_b,
    const float* __restrict__ W2, const float* __restrict__ b2,
    float* __restrict__ out)
{
    __shared__ float sh_fold[RGROUPS][KCHUNK];   // 8 KB
    __shared__ float sh_pool[KCHUNK];
    __shared__ float sh_gacc[2][ROUTE_H];
    __shared__ unsigned int s_flag;

    int blk = blockIdx.x;
    int b   = blk / GSPLIT;
    int sp  = blk % GSPLIT;
    int t   = threadIdx.x;           // 0..511
    int i0  = sp * KCHUNK;           // first hidden col of this block's slice

    // ---------------- Phase 1: column-slice mean-pool -----------------------
    // Thread (col4 = t&31, rg = t>>5) accumulates float4 column col4 over
    // rows rg, rg+16, ... (256 rows). Warp = 32 consecutive float4 = 512 B
    // contiguous -> fully coalesced. Two accumulators for ILP.
    {
        int col4 = t & (K4 - 1);
        int rg   = t >> 5;
        const float4* base = (const float4*)(x) +
            ((size_t)b * SEQ + rg) * (size_t)H4 + (i0 >> 2) + col4;

        float4 aA = make_float4(0.f, 0.f, 0.f, 0.f);
        float4 aB = make_float4(0.f, 0.f, 0.f, 0.f);
#pragma unroll 4
        for (int i = 0; i < RPT; i += 2) {
            float4 vA = __ldcs(&base[(size_t)(i)     * RGROUPS * H4]);
            float4 vB = __ldcs(&base[(size_t)(i + 1) * RGROUPS * H4]);
            aA.x += vA.x; aA.y += vA.y; aA.z += vA.z; aA.w += vA.w;
            aB.x += vB.x; aB.y += vB.y; aB.z += vB.z; aB.w += vB.w;
        }
        aA.x += aB.x; aA.y += aB.y; aA.z += aB.z; aA.w += aB.w;
        ((float4*)sh_fold[rg])[col4] = aA;
    }
    __syncthreads();

    // Fold the 16 row-groups (fixed order) -> pooled slice.
    if (t < KCHUNK) {
        float s0 = 0.f, s1 = 0.f, s2 = 0.f, s3 = 0.f;
#pragma unroll
        for (int g = 0; g < RGROUPS; g += 4) {
            s0 += sh_fold[g + 0][t];
            s1 += sh_fold[g + 1][t];
            s2 += sh_fold[g + 2][t];
            s3 += sh_fold[g + 3][t];
        }
        sh_pool[t] = ((s0 + s1) + (s2 + s3)) * (1.0f / SEQ);
    }
    __syncthreads();

    // ---------------- Phase 2: GEMV1 slice (starts immediately) ------------
    // 512 threads = 256 outputs x 2 row-halves of 64 rows, 8 accumulators.
    {
        int j    = t & (ROUTE_H - 1);
        int half = t >> 8;               // 0 or 1
        int r0   = i0 + half * 64;
        float a0 = 0.f, a1 = 0.f, a2 = 0.f, a3 = 0.f;
        float a4 = 0.f, a5 = 0.f, a6 = 0.f, a7 = 0.f;
#pragma unroll
        for (int r = 0; r < 64; r += 8) {
            const float* w = W1 + (size_t)(r0 + r) * ROUTE_H + j;
            int p = half * 64 + r;
            a0 += sh_pool[p + 0] * w[0 * ROUTE_H];
            a1 += sh_pool[p + 1] * w[1 * ROUTE_H];
            a2 += sh_pool[p + 2] * w[2 * ROUTE_H];
            a3 += sh_pool[p + 3] * w[3 * ROUTE_H];
            a4 += sh_pool[p + 4] * w[4 * ROUTE_H];
            a5 += sh_pool[p + 5] * w[5 * ROUTE_H];
            a6 += sh_pool[p + 6] * w[6 * ROUTE_H];
            a7 += sh_pool[p + 7] * w[7 * ROUTE_H];
        }
        sh_gacc[half][j] = ((a0 + a1) + (a2 + a3)) + ((a4 + a5) + (a6 + a7));
    }
    __syncthreads();
    if (t < ROUTE_H)
        g_hpart[((size_t)sp * BATCH + b) * ROUTE_H + t] =
            sh_gacc[0][t] + sh_gacc[1][t];

    // ---------------- election (no spin): last slice runs the finale -------
    __threadfence();                     // publish h-slice
    __syncthreads();
    if (t == 0) {
        unsigned int old = atomicAdd(&g_cnt[b], 1u);
        s_flag = (old == GSPLIT - 1) ? 1u : 0u;
    }
    __syncthreads();
    if (!s_flag) return;
    __threadfence();                     // acquire all 16 h-slices

    // ---------------- Phase 3: finale (first 256 threads) ------------------
    __shared__ float sh_h[ROUTE_H];
    __shared__ float sh_w1r[8], sh_w2r[8];
    __shared__ float sh_part[ROUTE_H];
    __shared__ float sh_logits[NUM_EXPERTS];

    if (t < ROUTE_H) {
        int j    = t;
        int lane = t & 31;
        int warp = t >> 5;

        float h = 0.f;
#pragma unroll
        for (int k = 0; k < GSPLIT; k++)
            h += g_hpart[((size_t)k * BATCH + b) * ROUTE_H + j];
        h += b1[j];

        // LN reduce via warp shuffles (8 warps)
        float s1 = h, s2 = h * h;
#pragma unroll
        for (int o = 16; o > 0; o >>= 1) {
            s1 += __shfl_xor_sync(0xffffffffu, s1, o);
            s2 += __shfl_xor_sync(0xffffffffu, s2, o);
        }
        if (lane == 0) { sh_w1r[warp] = s1; sh_w2r[warp] = s2; }
        __syncwarp();
        asm volatile("bar.sync 1, 256;" ::: "memory");
        float t1 = sh_w1r[lane & 7], t2 = sh_w2r[lane & 7];
#pragma unroll
        for (int o = 4; o > 0; o >>= 1) {
            t1 += __shfl_xor_sync(0xffffffffu, t1, o);
            t2 += __shfl_xor_sync(0xffffffffu, t2, o);
        }
        t1 = __shfl_sync(0xffffffffu, t1, 0);
        t2 = __shfl_sync(0xffffffffu, t2, 0);

        float mu  = t1 * (1.0f / ROUTE_H);
        float ms  = t2 * (1.0f / ROUTE_H);
        float inv = rsqrtf(ms - mu * mu + LN_EPS);
        h = (h - mu) * inv * ln_g[j] + ln_b[j];
        h = 0.5f * h * (1.0f + erff(h * 0.70710678118654752f)); // exact GELU
        sh_h[j] = h;
        asm volatile("bar.sync 1, 256;" ::: "memory");

        // GEMV2, K-split 4: 256 threads = 64 experts x 4 slices
        {
            int e   = j & (NUM_EXPERTS - 1);
            int ks2 = j >> 6;
            int r0  = ks2 * (ROUTE_H / 4);
            float a = 0.f;
#pragma unroll 8
            for (int i = 0; i < ROUTE_H / 4; i++)
                a += sh_h[r0 + i] * W2[(size_t)(r0 + i) * NUM_EXPERTS + e];
            sh_part[j] = a;
        }
        asm volatile("bar.sync 1, 256;" ::: "memory");
        if (j < NUM_EXPERTS) {
            sh_logits[j] = ((sh_part[j] + sh_part[j + 64]) +
                            (sh_part[j + 128] + sh_part[j + 192])) + b2[j];
            out[(size_t)b * NUM_EXPERTS + j] = 0.0f;   // d_out poisoned
        }
        asm volatile("bar.sync 1, 256;" ::: "memory");

        // top-8 + softmax + scatter (strict '>' = first-index tie-break,
        // matching jax.lax.top_k). Then reset the counter for graph replay.
        if (j == 0) {
            int   idx[TOP_K];
            float val[TOP_K];
            unsigned long long used = 0ull;
            for (int k = 0; k < TOP_K; k++) {
                float best = -INFINITY;
                int bi = 0;
                for (int e = 0; e < NUM_EXPERTS; e++) {
                    if (!((used >> e) & 1ull) && sh_logits[e] > best) {
                        best = sh_logits[e]; bi = e;
                    }
                }
                used |= (1ull << bi);
                idx[k] = bi;
                val[k] = best;
            }
            float mx = val[0];
            float denom = 0.f;
            float ex[TOP_K];
            for (int k = 0; k < TOP_K; k++) { ex[k] = expf(val[k] - mx); denom += ex[k]; }
            float rden = 1.0f / denom;
            for (int k = 0; k < TOP_K; k++)
                out[(size_t)b * NUM_EXPERTS + idx[k]] = ex[k] * rden;

            // all 16 increments for batch b happened before this finale ran
            g_cnt[b] = 0u;
        }
    }
}

// ---------------------------------------------------------------------------
extern "C" void kernel_launch(void* const* d_in, const int* in_sizes, int n_in,
                              void* d_out, int out_size) {
    const float* hs   = (const float*)d_in[0];
    const float* W1   = (const float*)d_in[1];
    const float* b1   = (const float*)d_in[2];
    const float* ln_g = (const float*)d_in[3];
    const float* ln_b = (const float*)d_in[4];
    const float* W2   = (const float*)d_in[5];
    const float* b2   = (const float*)d_in[6];
    // d_in[7] = top_k (hardcoded 8)

    float* out = (float*)d_out;

    fused_router<<<NBLK, NTHR>>>(hs, W1, b1, ln_g, ln_b, W2, b2, out);
}

// round 17
// speedup vs baseline: 1.1565x; 1.1257x over previous
#include <cuda_runtime.h>
#include <math.h>

#define BATCH 32
#define SEQ 4096
#define HIDDEN 2048
#define ROUTE_H 256
#define NUM_EXPERTS 64
#define TOP_K 8
#define LN_EPS 1e-5f

#define NSPLIT 16                    // blocks per batch (also K-split for GEMV1)
#define SCHUNK (SEQ / NSPLIT)        // 256 seq rows per block
#define H4 (HIDDEN / 4)              // 512 float4 columns
#define KCHUNK (HIDDEN / NSPLIT)     // 128 hidden cols per GEMV1 slice
#define NTHR 512

// Scratch (no cudaMalloc allowed). Zero-initialized at module load; counters
// are reset by the finale block each launch -> graph-replay safe.
__device__ float g_partial[NSPLIT * BATCH * HIDDEN];   // [sp][b][h] = 4 MB
__device__ float g_hpart[NSPLIT * BATCH * ROUTE_H];    // [ks][b][j] = 512 KB
__device__ unsigned int g_cnt1[BATCH];                 // pool-done election
__device__ unsigned int g_cnt2[BATCH];                 // gemv-done election

// ---------------------------------------------------------------------------
// ONE fused kernel. grid = BATCH*NSPLIT = 512 blocks x 512 threads = exactly
// one resident wave (<= 148 SMs x 4 CTAs) -> all blocks co-resident, so the
// per-batch spin-wait cannot deadlock. Spins use __nanosleep so waiting
// blocks don't steal issue slots / L2 bandwidth from still-streaming blocks.
// Phase 1: pool partial for (b, sp) with __ldcs streaming loads.
// Phase 2: sleep-spin until batch b fully pooled, fold (4 indep chains),
//          GEMV1 K-slice.
// Phase 3: last finishing block of batch b runs LN + GELU + GEMV2 + top-8.
// All reduction orders are fixed -> deterministic output.
// ---------------------------------------------------------------------------
__global__ void __launch_bounds__(NTHR) fused_router(
    const float* __restrict__ x,
    const float* __restrict__ W1, const float* __restrict__ b1,
    const float* __restrict__ ln_g, const float* __restrict__ ln_b,
    const float* __restrict__ W2, const float* __restrict__ b2,
    float* __restrict__ out)
{
    __shared__ float sh_fold[4][KCHUNK];
    __shared__ float sh_pool[KCHUNK];
    __shared__ float sh_gacc[2][ROUTE_H];
    __shared__ unsigned int s_flag;

    int blk = blockIdx.x;
    int b   = blk / NSPLIT;
    int sp  = blk % NSPLIT;
    int t   = threadIdx.x;           // 0..511

    // ---------------- Phase 1: partial mean-pool ----------------
    {
        const float4* base = (const float4*)(x) +
            ((size_t)b * SEQ + (size_t)sp * SCHUNK) * (size_t)H4 + t;
        float4 acc = make_float4(0.f, 0.f, 0.f, 0.f);
#pragma unroll 8
        for (int s = 0; s < SCHUNK; s++) {
            float4 v = __ldcs(&base[(size_t)s * H4]);
            acc.x += v.x; acc.y += v.y; acc.z += v.z; acc.w += v.w;
        }
        float4* o = (float4*)(g_partial + ((size_t)sp * BATCH + b) * HIDDEN);
        o[t] = acc;
    }

    // ---------------- arrive + sleep-spin until batch b pooled -------------
    __threadfence();                       // publish partials
    __syncthreads();
    if (t == 0) {
        atomicAdd(&g_cnt1[b], 1u);
        while (((volatile unsigned int*)g_cnt1)[b] < NSPLIT) {
            __nanosleep(256);              // free issue slots for streamers
        }
    }
    __syncthreads();
    __threadfence();                       // acquire all 16 partial slices

    // ---------------- Phase 2: GEMV1 K-slice for cols [sp*128, +128) -------
    int i0 = sp * KCHUNK;

    // Fold 16 partials for 128 columns: thread (col = t&127, part = t>>7)
    // folds 4 partials with 4 independent loads; combine below. (L2-hot.)
    {
        int col  = t & (KCHUNK - 1);
        int part = t >> 7;                 // 0..3
        const float* p = g_partial +
            ((size_t)part * 4 * BATCH + b) * HIDDEN + i0 + col;
        float f0 = p[0];
        float f1 = p[(size_t)1 * BATCH * HIDDEN];
        float f2 = p[(size_t)2 * BATCH * HIDDEN];
        float f3 = p[(size_t)3 * BATCH * HIDDEN];
        sh_fold[part][col] = (f0 + f1) + (f2 + f3);
    }
    __syncthreads();
    if (t < KCHUNK) {
        sh_pool[t] = ((sh_fold[0][t] + sh_fold[1][t]) +
                      (sh_fold[2][t] + sh_fold[3][t])) * (1.0f / SEQ);
    }
    __syncthreads();

    // GEMV slice: 512 threads = 256 outputs x 2 row-halves of 64 rows.
    // 8 independent accumulators; W1 reads coalesced across j.
    {
        int j    = t & (ROUTE_H - 1);
        int half = t >> 8;                 // 0 or 1
        int r0   = i0 + half * 64;
        float a0 = 0.f, a1 = 0.f, a2 = 0.f, a3 = 0.f;
        float a4 = 0.f, a5 = 0.f, a6 = 0.f, a7 = 0.f;
#pragma unroll
        for (int r = 0; r < 64; r += 8) {
            const float* w = W1 + (size_t)(r0 + r) * ROUTE_H + j;
            int p = half * 64 + r;
            a0 += sh_pool[p + 0] * w[0 * ROUTE_H];
            a1 += sh_pool[p + 1] * w[1 * ROUTE_H];
            a2 += sh_pool[p + 2] * w[2 * ROUTE_H];
            a3 += sh_pool[p + 3] * w[3 * ROUTE_H];
            a4 += sh_pool[p + 4] * w[4 * ROUTE_H];
            a5 += sh_pool[p + 5] * w[5 * ROUTE_H];
            a6 += sh_pool[p + 6] * w[6 * ROUTE_H];
            a7 += sh_pool[p + 7] * w[7 * ROUTE_H];
        }
        sh_gacc[half][j] = ((a0 + a1) + (a2 + a3)) + ((a4 + a5) + (a6 + a7));
    }
    __syncthreads();
    if (t < ROUTE_H)
        g_hpart[((size_t)sp * BATCH + b) * ROUTE_H + t] =
            sh_gacc[0][t] + sh_gacc[1][t];

    // ---------------- election: last GEMV block runs the finale ------------
    __threadfence();                       // publish h-partial slice
    __syncthreads();
    if (t == 0) {
        unsigned int old = atomicAdd(&g_cnt2[b], 1u);
        s_flag = (old == NSPLIT - 1) ? 1u : 0u;
    }
    __syncthreads();
    if (!s_flag) return;
    __threadfence();                       // acquire all 16 h-slices

    // ---------------- Phase 3: finale (first 256 threads) ------------------
    __shared__ float sh_h[ROUTE_H];
    __shared__ float sh_w1r[8], sh_w2r[8];
    __shared__ float sh_part[ROUTE_H];
    __shared__ float sh_logits[NUM_EXPERTS];

    if (t < ROUTE_H) {
        int j    = t;
        int lane = t & 31;
        int warp = t >> 5;

        float h = 0.f;
#pragma unroll
        for (int k = 0; k < NSPLIT; k++)
            h += g_hpart[((size_t)k * BATCH + b) * ROUTE_H + j];
        h += b1[j];

        // LN reduce via warp shuffles (8 warps)
        float s1 = h, s2 = h * h;
#pragma unroll
        for (int o = 16; o > 0; o >>= 1) {
            s1 += __shfl_xor_sync(0xffffffffu, s1, o);
            s2 += __shfl_xor_sync(0xffffffffu, s2, o);
        }
        if (lane == 0) { sh_w1r[warp] = s1; sh_w2r[warp] = s2; }
        __syncwarp();
        asm volatile("bar.sync 1, 256;" ::: "memory");
        float t1 = sh_w1r[lane & 7], t2 = sh_w2r[lane & 7];
#pragma unroll
        for (int o = 4; o > 0; o >>= 1) {
            t1 += __shfl_xor_sync(0xffffffffu, t1, o);
            t2 += __shfl_xor_sync(0xffffffffu, t2, o);
        }
        t1 = __shfl_sync(0xffffffffu, t1, 0);
        t2 = __shfl_sync(0xffffffffu, t2, 0);

        float mu  = t1 * (1.0f / ROUTE_H);
        float ms  = t2 * (1.0f / ROUTE_H);
        float inv = rsqrtf(ms - mu * mu + LN_EPS);
        h = (h - mu) * inv * ln_g[j] + ln_b[j];
        h = 0.5f * h * (1.0f + erff(h * 0.70710678118654752f)); // exact GELU
        sh_h[j] = h;
        asm volatile("bar.sync 1, 256;" ::: "memory");

        // GEMV2, K-split 4: 256 threads = 64 experts x 4 slices
        {
            int e   = j & (NUM_EXPERTS - 1);
            int ks2 = j >> 6;
            int r0  = ks2 * (ROUTE_H / 4);
            float a = 0.f;
#pragma unroll 8
            for (int i = 0; i < ROUTE_H / 4; i++)
                a += sh_h[r0 + i] * W2[(size_t)(r0 + i) * NUM_EXPERTS + e];
            sh_part[j] = a;
        }
        asm volatile("bar.sync 1, 256;" ::: "memory");
        if (j < NUM_EXPERTS) {
            sh_logits[j] = ((sh_part[j] + sh_part[j + 64]) +
                            (sh_part[j + 128] + sh_part[j + 192])) + b2[j];
            out[(size_t)b * NUM_EXPERTS + j] = 0.0f;  // d_out poisoned
        }
        asm volatile("bar.sync 1, 256;" ::: "memory");

        // top-8 + softmax + scatter (strict '>' = first-index tie-break,
        // matching jax.lax.top_k). Also reset counters for next graph replay.
        if (j == 0) {
            int   idx[TOP_K];
            float val[TOP_K];
            unsigned long long used = 0ull;
            for (int k = 0; k < TOP_K; k++) {
                float best = -INFINITY;
                int bi = 0;
                for (int e = 0; e < NUM_EXPERTS; e++) {
                    if (!((used >> e) & 1ull) && sh_logits[e] > best) {
                        best = sh_logits[e]; bi = e;
                    }
                }
                used |= (1ull << bi);
                idx[k] = bi;
                val[k] = best;
            }
            float mx = val[0];
            float denom = 0.f;
            float ex[TOP_K];
            for (int k = 0; k < TOP_K; k++) { ex[k] = expf(val[k] - mx); denom += ex[k]; }
            float rden = 1.0f / denom;
            for (int k = 0; k < TOP_K; k++)
                out[(size_t)b * NUM_EXPERTS + idx[k]] = ex[k] * rden;

            g_cnt1[b] = 0u;   // reset for next replay (all uses complete)
            g_cnt2[b] = 0u;
        }
    }
}

// ---------------------------------------------------------------------------
extern "C" void kernel_launch(void* const* d_in, const int* in_sizes, int n_in,
                              void* d_out, int out_size) {
    const float* hs   = (const float*)d_in[0];
    const float* W1   = (const float*)d_in[1];
    const float* b1   = (const float*)d_in[2];
    const float* ln_g = (const float*)d_in[3];
    const float* ln_b = (const float*)d_in[4];
    const float* W2   = (const float*)d_in[5];
    const float* b2   = (const float*)d_in[6];
    // d_in[7] = top_k (hardcoded 8)

    float* out = (float*)d_out;

    fused_router<<<BATCH * NSPLIT, NTHR>>>(hs, W1, b1, ln_g, ln_b, W2, b2, out);
}